// round 1
// baseline (speedup 1.0000x reference)
#include <cuda_runtime.h>

#define B_ROWS 16384
#define IN_DIM 2048
#define E_NUM 16
#define KMAX 8

#define TEMP_F 0.7f
#define P_MIN_F 0.92f
#define CLOSE_F 0.82f   // P_MIN - CLOSE_DELTA

#define SC_OFF (B_ROWS * KMAX)          // 131072
#define MK_OFF (2 * B_ROWS * KMAX)      // 262144
#define KV_OFF (3 * B_ROWS * KMAX)      // 393216

__global__ __launch_bounds__(256) void dyn_top_gate_kernel(
    const float* __restrict__ x,
    const float* __restrict__ W1,
    const float* __restrict__ W2,
    float* __restrict__ out)
{
    const int warp_id = blockIdx.x * (blockDim.x >> 5) + (threadIdx.x >> 5);
    const int lane = threadIdx.x & 31;
    const int row0 = warp_id * 4;
    if (row0 >= B_ROWS) return;

    // ---------------- GEMM: h_pre[e][r] = dot(x[row], W1[e]) ----------------
    float acc[64];
#pragma unroll
    for (int i = 0; i < 64; i++) acc[i] = 0.f;

    const float* xr0 = x + (size_t)(row0 + 0) * IN_DIM;
    const float* xr1 = x + (size_t)(row0 + 1) * IN_DIM;
    const float* xr2 = x + (size_t)(row0 + 2) * IN_DIM;
    const float* xr3 = x + (size_t)(row0 + 3) * IN_DIM;

#pragma unroll 1
    for (int k0 = lane * 4; k0 < IN_DIM; k0 += 128) {
        float4 xv0 = *reinterpret_cast<const float4*>(xr0 + k0);
        float4 xv1 = *reinterpret_cast<const float4*>(xr1 + k0);
        float4 xv2 = *reinterpret_cast<const float4*>(xr2 + k0);
        float4 xv3 = *reinterpret_cast<const float4*>(xr3 + k0);
#pragma unroll
        for (int e = 0; e < E_NUM; e++) {
            float4 w = *reinterpret_cast<const float4*>(W1 + (size_t)e * IN_DIM + k0);
            acc[e * 4 + 0] = fmaf(w.x, xv0.x, acc[e * 4 + 0]);
            acc[e * 4 + 0] = fmaf(w.y, xv0.y, acc[e * 4 + 0]);
            acc[e * 4 + 0] = fmaf(w.z, xv0.z, acc[e * 4 + 0]);
            acc[e * 4 + 0] = fmaf(w.w, xv0.w, acc[e * 4 + 0]);
            acc[e * 4 + 1] = fmaf(w.x, xv1.x, acc[e * 4 + 1]);
            acc[e * 4 + 1] = fmaf(w.y, xv1.y, acc[e * 4 + 1]);
            acc[e * 4 + 1] = fmaf(w.z, xv1.z, acc[e * 4 + 1]);
            acc[e * 4 + 1] = fmaf(w.w, xv1.w, acc[e * 4 + 1]);
            acc[e * 4 + 2] = fmaf(w.x, xv2.x, acc[e * 4 + 2]);
            acc[e * 4 + 2] = fmaf(w.y, xv2.y, acc[e * 4 + 2]);
            acc[e * 4 + 2] = fmaf(w.z, xv2.z, acc[e * 4 + 2]);
            acc[e * 4 + 2] = fmaf(w.w, xv2.w, acc[e * 4 + 2]);
            acc[e * 4 + 3] = fmaf(w.x, xv3.x, acc[e * 4 + 3]);
            acc[e * 4 + 3] = fmaf(w.y, xv3.y, acc[e * 4 + 3]);
            acc[e * 4 + 3] = fmaf(w.z, xv3.z, acc[e * 4 + 3]);
            acc[e * 4 + 3] = fmaf(w.w, xv3.w, acc[e * 4 + 3]);
        }
    }

    // ---------------- warp reduce all 64 partial sums ----------------
#pragma unroll
    for (int off = 16; off > 0; off >>= 1) {
#pragma unroll
        for (int i = 0; i < 64; i++)
            acc[i] += __shfl_xor_sync(0xffffffffu, acc[i], off);
    }
    // every lane now holds the full pre-tanh h for all (e, r)

    // ---------------- epilogue: half-warp per row pair ----------------
    // lane = f + 16*g ; g=0 handles local rows {0,1}, g=1 handles {2,3}
    const int g = lane >> 4;
    const int f = lane & 15;

    // per-lane W2 row (f fixed): logits[b][f] = sum_e h[b][e] * W2[f][e]
    float w2f[E_NUM];
#pragma unroll
    for (int e = 0; e < E_NUM; e++) w2f[e] = __ldg(W2 + f * E_NUM + e);

#pragma unroll
    for (int rr = 0; rr < 2; rr++) {
        const int r_local = 2 * g + rr;
        const int row = row0 + r_local;

        // h for this row (tanh), then logit for expert f
        float logit = 0.f;
#pragma unroll
        for (int e = 0; e < E_NUM; e++) {
            float h = tanhf(acc[e * 4 + r_local]);
            logit = fmaf(h, w2f[e], logit);
        }
        logit = logit / TEMP_F;

        // max over the 16-lane segment
        float m = logit;
#pragma unroll
        for (int s = 8; s > 0; s >>= 1)
            m = fmaxf(m, __shfl_xor_sync(0xffffffffu, m, s, 16));

        float ex = expf(logit - m);
        float sum = ex;
#pragma unroll
        for (int s = 8; s > 0; s >>= 1)
            sum += __shfl_xor_sync(0xffffffffu, sum, s, 16);
        float prob = ex / sum;

        // stable descending rank (ties broken by smaller expert index first)
        int rank = 0;
#pragma unroll
        for (int g2 = 0; g2 < E_NUM; g2++) {
            float lv = __shfl_sync(0xffffffffu, logit, g2, 16);
            rank += (lv > logit) || (lv == logit && g2 < f);
        }

        // inclusive cumulative prob at my rank; pick p1,p2,p3
        float cum = 0.f, p1 = 0.f, p2 = 0.f, p3 = 0.f;
#pragma unroll
        for (int g2 = 0; g2 < E_NUM; g2++) {
            float pv = __shfl_sync(0xffffffffu, prob, g2, 16);
            int rv = __shfl_sync(0xffffffffu, rank, g2, 16);
            if (rv <= rank) cum += pv;
            if (rv == 0) p1 = pv;
            if (rv == 1) p2 = pv;
            if (rv == 2) p3 = pv;
        }

        // idx_first = #ranks with cum < P_MIN (cum monotone in rank)
        int cnt = 0;
#pragma unroll
        for (int g2 = 0; g2 < E_NUM; g2++) {
            float cv = __shfl_sync(0xffffffffu, cum, g2, 16);
            cnt += (cv < P_MIN_F);
        }
        if (cnt > E_NUM - 1) cnt = E_NUM - 1;
        int kv = cnt + 1;

        float gap12 = p1 - p2;
        float gap23 = p2 - p3;
        if (p1 >= 0.46f && gap12 >= 0.1f) kv = 1;
        float cum1 = p1 + p2;
        if (kv > 2 && (cum1 >= CLOSE_F || p3 <= 0.12f || gap23 <= 0.03f)) kv = 2;
        kv = max(1, min(3, kv));

        // ---------------- writes ----------------
        if (rank < KMAX) {
            int o = row * KMAX + rank;
            out[o] = (float)f;                                   // top_indices
            out[SC_OFF + o] = (rank < kv) ? prob : 0.f;          // top_scores
            out[MK_OFF + o] = (rank < kv) ? 1.f : 0.f;           // top_mask
        }
        if (rank == 0) out[KV_OFF + row] = (float)kv;            // k_vec
    }
}

extern "C" void kernel_launch(void* const* d_in, const int* in_sizes, int n_in,
                              void* d_out, int out_size) {
    const float* x  = (const float*)d_in[0];
    const float* W1 = (const float*)d_in[1];
    const float* W2 = (const float*)d_in[2];
    float* out = (float*)d_out;

    // 4 rows per warp, 8 warps per block -> 32 rows/block
    const int blocks = B_ROWS / 32;  // 512
    dyn_top_gate_kernel<<<blocks, 256>>>(x, W1, W2, out);
}